// round 8
// baseline (speedup 1.0000x reference)
#include <cuda_runtime.h>
#include <math.h>

// Problem constants
#define Bsz 2
#define Nn  2048
#define Dd  1024
#define Hh  16
#define HDh 64
#define Rr  (Bsz * Nn)          // 4096 rows total

// Scratch (no allocation allowed -> device globals)
__device__ float g_hf[Rr * Dd];        // [4096,1024] per-head value features
__device__ float g_T[Rr * Dd];         // [4096,1024] gelu activations (concat heads)
__device__ float g_Wt[Dd * Dd];        // blockdiag(w2) @ out_proj
__device__ float g_Wbig[Dd * Dd];      // Wt @ o_proj
__device__ float g_Vcat[Dd * Dd];      // vproj repacked [D, H*HD]
__device__ float g_partial[Bsz * 64 * Dd]; // partial column sums for mean
__device__ float g_c[Bsz * Hh * HDh];  // per-(b,head) folded bias
__device__ float g_v1[Dd];             // b2cat @ out_proj
__device__ float g_zbias[Dd];          // (b2cat @ out_proj) @ o_proj

// =========================================================================
// tf32 mma.sync GEMM, 128x128x32 tile, 256 thr (8 warps), N and K fixed 1024.
// Fragment-order SMEM, register prefetch, two-stage smem buffer (one
// __syncthreads per k-iter). Optional per-column bias add in epilogue.
// __launch_bounds__(256,2): 2 CTAs/SM (135KB dyn smem total, regs<=128).
// =========================================================================
__device__ __forceinline__ unsigned f2tf32(float v)
{
    unsigned o;
    asm volatile("cvt.rna.tf32.f32 %0, %1;\n" : "=r"(o) : "f"(v));
    return o;
}

__device__ __forceinline__ void mma_tf32(
    float& c0, float& c1, float& c2, float& c3,
    unsigned a0, unsigned a1, unsigned a2, unsigned a3,
    unsigned b0, unsigned b1)
{
    asm volatile(
        "mma.sync.aligned.m16n8k8.row.col.f32.tf32.tf32.f32 "
        "{%0,%1,%2,%3},{%4,%5,%6,%7},{%8,%9},{%0,%1,%2,%3};\n"
        : "+f"(c0), "+f"(c1), "+f"(c2), "+f"(c3)
        : "r"(a0), "r"(a1), "r"(a2), "r"(a3), "r"(b0), "r"(b1));
}

// A: 32 groups (mt 0..7, ks 0..3) of 32 lanes x 4 words, padded 128->132
// B: 64 groups (nt 0..15, ks 0..3) of 32 lanes x 2 words, padded 64->66
#define AGRP 132
#define BGRP 66
#define STGW (32 * AGRP + 64 * BGRP)     // words per stage = 8448
#define GEMM_SMEM_BYTES (2 * STGW * 4)   // 67584

extern __shared__ unsigned dynsmem[];

__global__ __launch_bounds__(256, 2) void gemm_tf32(
    const float* __restrict__ A0, const float* __restrict__ B0,
    float* __restrict__ C0, const float* __restrict__ bias0,
    const float* __restrict__ A1, const float* __restrict__ B1,
    float* __restrict__ C1, const float* __restrict__ bias1,
    int blocks0)
{
    const float* A; const float* Bm; float* C; const float* bias; int rb;
    if ((int)blockIdx.x < blocks0) {
        A = A0; Bm = B0; C = C0; bias = bias0; rb = blockIdx.x;
    } else {
        A = A1; Bm = B1; C = C1; bias = bias1; rb = blockIdx.x - blocks0;
    }

    const int row0 = (rb >> 3) * 128;
    const int col0 = (rb & 7) * 128;

    const int tid    = threadIdx.x;
    const int lane   = tid & 31;
    const int wid    = tid >> 5;
    const int warp_m = wid & 1;          // 64 rows
    const int warp_n = wid >> 1;         // 32 cols

    // ---- precomputed store indices (stage-relative) ----
    float4 pa[4], pb[4];
    const float* Arow[4];
    const float* Brow[4];
    int aidx[4], bidx[4];
#pragma unroll
    for (int i = 0; i < 4; i++) {
        int f = i * 256 + tid;
        int r = f >> 3, q = f & 7;
        Arow[i] = A + (long)(row0 + r) * Dd + q * 4;
        int mt = r >> 4, rr = r & 15;
        int rp = rr & 7, hi = rr >> 3;
        int ks = q >> 1, ch = q & 1;
        aidx[i] = ((mt * 4 + ks) * AGRP) + (rp * 4) * 4 + (hi + 2 * ch);
        int kr = f >> 5, qn = f & 31;
        Brow[i] = Bm + (long)kr * Dd + col0 + qn * 4;
        int nt = qn >> 1, g0 = (qn & 1) * 4;
        int ksb = kr >> 3, slotb = (kr >> 2) & 1;
        bidx[i] = 32 * AGRP + ((nt * 4 + ksb) * BGRP) + (g0 * 4 + (kr & 3)) * 2 + slotb;
    }

    float acc[4][4][4];
#pragma unroll
    for (int i = 0; i < 4; i++)
#pragma unroll
        for (int j = 0; j < 4; j++)
#pragma unroll
            for (int q = 0; q < 4; q++) acc[i][j][q] = 0.0f;

    // prefetch k-tile 0
#pragma unroll
    for (int i = 0; i < 4; i++) { pa[i] = *(const float4*)Arow[i];
                                  pb[i] = *(const float4*)Brow[i]; }

    for (int it = 0; it < 32; it++) {
        unsigned* S = dynsmem + (it & 1) * STGW;

        // ---- store prefetched tile into fragment-order smem (this stage) ----
#pragma unroll
        for (int i = 0; i < 4; i++) {
            S[aidx[i] + 0]  = f2tf32(pa[i].x);
            S[aidx[i] + 4]  = f2tf32(pa[i].y);
            S[aidx[i] + 8]  = f2tf32(pa[i].z);
            S[aidx[i] + 12] = f2tf32(pa[i].w);
            S[bidx[i] + 0]  = f2tf32(pb[i].x);
            S[bidx[i] + 8]  = f2tf32(pb[i].y);
            S[bidx[i] + 16] = f2tf32(pb[i].z);
            S[bidx[i] + 24] = f2tf32(pb[i].w);
        }

        // ---- prefetch next k-tile (A: +k elems; B: +k rows) ----
        if (it < 31) {
            int kn = (it + 1) * 32;
#pragma unroll
            for (int i = 0; i < 4; i++) {
                pa[i] = *(const float4*)(Arow[i] + kn);
                pb[i] = *(const float4*)(Brow[i] + (long)kn * Dd);
            }
        }

        __syncthreads();   // single barrier per iteration (2-stage buffer)

        const unsigned* Sa = S;
#pragma unroll
        for (int ks = 0; ks < 4; ks++) {
            uint4 a[4]; uint2 b[4];
#pragma unroll
            for (int mi = 0; mi < 4; mi++)
                a[mi] = *(const uint4*)&Sa[((warp_m * 4 + mi) * 4 + ks) * AGRP + lane * 4];
#pragma unroll
            for (int ni = 0; ni < 4; ni++)
                b[ni] = *(const uint2*)&Sa[32 * AGRP + ((warp_n * 4 + ni) * 4 + ks) * BGRP + lane * 2];
#pragma unroll
            for (int mi = 0; mi < 4; mi++)
#pragma unroll
                for (int ni = 0; ni < 4; ni++)
                    mma_tf32(acc[mi][ni][0], acc[mi][ni][1],
                             acc[mi][ni][2], acc[mi][ni][3],
                             a[mi].x, a[mi].y, a[mi].z, a[mi].w,
                             b[ni].x, b[ni].y);
        }
        // no trailing sync: next iteration writes the OTHER stage
    }

#pragma unroll
    for (int mi = 0; mi < 4; mi++) {
        int r = row0 + warp_m * 64 + mi * 16 + (lane >> 2);
#pragma unroll
        for (int ni = 0; ni < 4; ni++) {
            int c = col0 + warp_n * 32 + ni * 8 + 2 * (lane & 3);
            float2 v0 = make_float2(acc[mi][ni][0], acc[mi][ni][1]);
            float2 v1 = make_float2(acc[mi][ni][2], acc[mi][ni][3]);
            if (bias) {
                float b0 = bias[c], b1 = bias[c + 1];
                v0.x += b0; v0.y += b1;
                v1.x += b0; v1.y += b1;
            }
            *(float2*)(C + (long)r * Dd + c) = v0;
            *(float2*)(C + (long)(r + 8) * Dd + c) = v1;
        }
    }
}

// -------------------------------------------------------------------------
// Repack vproj [H][D][HD] -> Vcat [D][H*HD]
// -------------------------------------------------------------------------
__global__ __launch_bounds__(256) void repack_vcat(const float* __restrict__ vproj)
{
    int idx = blockIdx.x * 256 + threadIdx.x;   // 0..2^20-1
    int j = idx & 63;
    int k = (idx >> 6) & 1023;
    int h = idx >> 16;
    g_Vcat[(long)k * Dd + h * HDh + j] = vproj[idx];
}

// -------------------------------------------------------------------------
// Wt[h*64+m, :] = sum_j w2[h][m][j] * out_proj[h*64+j, :]
// grid (H, 8): per head, 128-col block. block 256 = 8 rowgroups x 32 colgroups.
// -------------------------------------------------------------------------
__global__ __launch_bounds__(256) void wt_kernel(
    const float* __restrict__ fus_w2, const float* __restrict__ out_proj)
{
    __shared__ float w2s[HDh][HDh];
    __shared__ float ops[HDh][128];

    const int hi = blockIdx.x;
    const int c0 = blockIdx.y * 128;
    const int tid = threadIdx.x;

    const float* w2 = fus_w2 + (long)hi * HDh * HDh;
#pragma unroll
    for (int i = 0; i < 4; i++) {           // 1024 float4 of w2
        int f = i * 256 + tid;
        *(float4*)&w2s[f >> 4][(f & 15) * 4] = *(const float4*)(w2 + f * 4);
    }
#pragma unroll
    for (int i = 0; i < 8; i++) {           // 2048 float4 of OP block
        int f = i * 256 + tid;
        int r = f >> 5, q = f & 31;
        *(float4*)&ops[r][q * 4] =
            *(const float4*)(out_proj + (long)(hi * HDh + r) * Dd + c0 + q * 4);
    }
    __syncthreads();

    const int rg = tid >> 5;                // 0..7 -> rows rg*8..+8
    const int tc = tid & 31;                // cols tc*4..+4
    float accw[8][4];
#pragma unroll
    for (int i = 0; i < 8; i++)
#pragma unroll
        for (int j = 0; j < 4; j++) accw[i][j] = 0.0f;

#pragma unroll 4
    for (int j = 0; j < HDh; j++) {
        float4 ov = *(float4*)&ops[j][tc * 4];
#pragma unroll
        for (int i = 0; i < 8; i++) {
            float w = w2s[rg * 8 + i][j];
            accw[i][0] += w * ov.x;
            accw[i][1] += w * ov.y;
            accw[i][2] += w * ov.z;
            accw[i][3] += w * ov.w;
        }
    }
#pragma unroll
    for (int i = 0; i < 8; i++) {
        float4 v = make_float4(accw[i][0], accw[i][1], accw[i][2], accw[i][3]);
        *(float4*)(g_Wt + (long)(hi * HDh + rg * 8 + i) * Dd + c0 + tc * 4) = v;
    }
}

// -------------------------------------------------------------------------
// zbias chain: v1 = b2cat @ out_proj ; zbias = v1 @ o_proj
// vec [1024] times mat [1024,1024]: grid 4, block 256, one column per thread.
// -------------------------------------------------------------------------
__global__ __launch_bounds__(256) void vecmat_kernel(
    const float* __restrict__ vec, const float* __restrict__ mat,
    float* __restrict__ outv)
{
    int c = blockIdx.x * 256 + threadIdx.x;
    float s = 0.0f;
    for (int j = 0; j < Dd; j++) s += vec[j] * mat[(long)j * Dd + c];
    outv[c] = s;
}

// -------------------------------------------------------------------------
// Deterministic mean: stage 1, 32-row partial sums. grid (64, B), block 1024.
// -------------------------------------------------------------------------
__global__ __launch_bounds__(1024) void mean_partial_kernel()
{
    int j  = threadIdx.x;
    int nc = blockIdx.x;
    int b  = blockIdx.y;
    const float* base = g_hf + ((long)b * Nn + nc * 32) * Dd + j;
    float s = 0.0f;
#pragma unroll 8
    for (int n = 0; n < 32; n++) s += base[(long)n * Dd];
    g_partial[((long)b * 64 + nc) * Dd + j] = s;
}

// -------------------------------------------------------------------------
// c[b,h,k] = fus_b1[h,k] + sum_m mean[b,h,m] * (w1[h,64+m,k] + w1[h,128+m,k])
// Block 256 = 64 k-lanes x 4 m-groups; deterministic fixed-order reduction.
// -------------------------------------------------------------------------
__global__ __launch_bounds__(256) void compute_c_kernel(
    const float* __restrict__ fus_w1, const float* __restrict__ fus_b1)
{
    int hi = blockIdx.x, b = blockIdx.y;
    int k = threadIdx.x & 63;
    int g = threadIdx.x >> 6;           // 0..3
    __shared__ float mean_s[HDh];
    __shared__ float part[4][HDh];
    __shared__ float part2[4][HDh];

    float s = 0.0f;
    for (int nc = g * 16; nc < g * 16 + 16; nc++)
        s += g_partial[((long)b * 64 + nc) * Dd + hi * HDh + k];
    part[g][k] = s;
    __syncthreads();
    if (g == 0) {
        float m = ((part[0][k] + part[1][k]) + part[2][k]) + part[3][k];
        mean_s[k] = m * (1.0f / (float)Nn);
    }
    __syncthreads();

    const float* w1 = fus_w1 + (long)hi * 192 * HDh;
    float acc = 0.0f;
#pragma unroll 4
    for (int m = g * 16; m < g * 16 + 16; m++)
        acc += mean_s[m] * (w1[(64 + m) * HDh + k] + w1[(128 + m) * HDh + k]);
    part2[g][k] = acc;
    __syncthreads();
    if (g == 0) {
        float v = fus_b1[hi * HDh + k]
                + ((part2[0][k] + part2[1][k]) + part2[2][k]) + part2[3][k];
        g_c[((long)b * Hh + hi) * HDh + k] = v;
    }
}

__device__ __forceinline__ float gelu_exact(float x)
{
    return 0.5f * x * (1.0f + erff(x * 0.70710678118654752440f));
}

// -------------------------------------------------------------------------
// Fusion layer 1 only: T = gelu(hf_head @ w1[:64] + c[b,h])
// (w2/b2 folded into Wbig/zbias.) Block: 64 rows x 64 cols, 256 threads, 4x4.
// -------------------------------------------------------------------------
__global__ __launch_bounds__(256) void fusion_kernel(
    const float* __restrict__ fus_w1)
{
    __shared__ float hfs[HDh][HDh];
    __shared__ float w1s[HDh][HDh];

    const int hi = blockIdx.y;
    const int r0 = blockIdx.x * 64;
    const int b  = r0 / Nn;
    const int tid = threadIdx.x;
    const int tr = tid >> 4;          // 0..15, 4 rows each
    const int tc = tid & 15;          // 0..15, 4 cols each

    const float* w1 = fus_w1 + (long)hi * 192 * HDh;  // first 64 rows used

#pragma unroll
    for (int i = 0; i < 4; i++) {
        int f = i * 256 + tid;        // float4 index 0..1023
        int m = f >> 4, q = f & 15;
        *(float4*)&w1s[m][q * 4] = *(const float4*)(w1 + m * 64 + q * 4);
        int rl = f >> 4;
        *(float4*)&hfs[rl][q * 4] =
            *(const float4*)(g_hf + (long)(r0 + rl) * Dd + hi * HDh + q * 4);
    }
    float cv[4];
#pragma unroll
    for (int j = 0; j < 4; j++)
        cv[j] = g_c[((long)b * Hh + hi) * HDh + tc * 4 + j];
    __syncthreads();

    float acc[4][4];
#pragma unroll
    for (int i = 0; i < 4; i++)
#pragma unroll
        for (int j = 0; j < 4; j++) acc[i][j] = cv[j];

#pragma unroll 4
    for (int m = 0; m < HDh; m++) {
        float4 wv = *(float4*)&w1s[m][tc * 4];
        float hv[4];
#pragma unroll
        for (int i = 0; i < 4; i++) hv[i] = hfs[tr * 4 + i][m];
#pragma unroll
        for (int i = 0; i < 4; i++) {
            acc[i][0] += hv[i] * wv.x;
            acc[i][1] += hv[i] * wv.y;
            acc[i][2] += hv[i] * wv.z;
            acc[i][3] += hv[i] * wv.w;
        }
    }
#pragma unroll
    for (int i = 0; i < 4; i++) {
        float4 v = make_float4(gelu_exact(acc[i][0]), gelu_exact(acc[i][1]),
                               gelu_exact(acc[i][2]), gelu_exact(acc[i][3]));
        *(float4*)(g_T + (long)(r0 + tr * 4 + i) * Dd + hi * HDh + tc * 4) = v;
    }
}

// -------------------------------------------------------------------------
// Tail outputs (constants), only if the output buffer carries them.
// -------------------------------------------------------------------------
__global__ void tail_kernel(float* __restrict__ out, int out_size)
{
    const int base = Rr * Dd;
    int i = blockIdx.x * blockDim.x + threadIdx.x;
    if (out_size >= base + 2 * Rr) {
        float strength = 1.0f - logf(1.0f / (float)Nn + 1e-8f);
        if (i < Rr)            out[base + i] = 1023.0f;
        else if (i < 2 * Rr)   out[base + i] = strength;
    }
}

// -------------------------------------------------------------------------
extern "C" void kernel_launch(void* const* d_in, const int* in_sizes, int n_in,
                              void* d_out, int out_size)
{
    const float* h         = (const float*)d_in[0];
    // d_in[1..8]: fe/be scorer weights -> provably dead (uniform softmax)
    const float* vproj_w   = (const float*)d_in[9];
    const float* fus_w1    = (const float*)d_in[10];
    const float* fus_b1    = (const float*)d_in[11];
    const float* fus_w2    = (const float*)d_in[12];
    const float* fus_b2    = (const float*)d_in[13];
    const float* out_proj  = (const float*)d_in[14];
    const float* o_proj    = (const float*)d_in[15];
    float* z = (float*)d_out;

    float *hf_p, *T_p, *Wt_p, *Wbig_p, *vcat_p, *v1_p, *zb_p;
    cudaGetSymbolAddress((void**)&hf_p,   g_hf);
    cudaGetSymbolAddress((void**)&T_p,    g_T);
    cudaGetSymbolAddress((void**)&Wt_p,   g_Wt);
    cudaGetSymbolAddress((void**)&Wbig_p, g_Wbig);
    cudaGetSymbolAddress((void**)&vcat_p, g_Vcat);
    cudaGetSymbolAddress((void**)&v1_p,   g_v1);
    cudaGetSymbolAddress((void**)&zb_p,   g_zbias);

    static int smem_set = 0;
    if (!smem_set) {
        cudaFuncSetAttribute(gemm_tf32,
                             cudaFuncAttributeMaxDynamicSharedMemorySize,
                             GEMM_SMEM_BYTES);
        smem_set = 1;
    }

    // 0) small precomputes: Vcat repack, Wt = BD(w2)@out_proj, zbias chain
    repack_vcat<<<(Dd * Dd) / 256, 256>>>(vproj_w);
    {
        dim3 gw(Hh, 8);
        wt_kernel<<<gw, 256>>>(fus_w2, out_proj);
    }
    vecmat_kernel<<<4, 256>>>(fus_b2, out_proj, v1_p);   // fus_b2 is [H*HD]=1024
    vecmat_kernel<<<4, 256>>>(v1_p, o_proj, zb_p);

    // 1+2) hf = h @ Vcat  AND  Wbig = Wt @ o_proj, one packed launch
    gemm_tf32<<<320, 256, GEMM_SMEM_BYTES>>>(
        h, vcat_p, hf_p, (const float*)0,
        Wt_p, o_proj, Wbig_p, (const float*)0, 256);

    // 3) deterministic mean over sequence + folded bias c
    {
        dim3 grid(64, Bsz);
        mean_partial_kernel<<<grid, 1024>>>();
        dim3 gridc(Hh, Bsz);
        compute_c_kernel<<<gridc, 256>>>(fus_w1, fus_b1);
    }
    // 4) fusion layer 1 -> T
    {
        dim3 grid(Rr / 64, Hh);
        fusion_kernel<<<grid, 256>>>(fus_w1);
    }
    // 5) z = T @ Wbig + zbias   (writes directly into d_out)
    gemm_tf32<<<256, 256, GEMM_SMEM_BYTES>>>(
        T_p, Wbig_p, z, zb_p,
        T_p, Wbig_p, z, zb_p, 256);

    // 6) constant tail outputs
    tail_kernel<<<32, 256>>>(z, out_size);
}

// round 10
// speedup vs baseline: 1.3208x; 1.3208x over previous
#include <cuda_runtime.h>
#include <math.h>

// Problem constants
#define Bsz 2
#define Nn  2048
#define Dd  1024
#define Hh  16
#define HDh 64
#define Rr  (Bsz * Nn)          // 4096 rows total

// Scratch (no allocation allowed -> device globals)
__device__ float g_hf[Rr * Dd];        // [4096,1024] per-head value features
__device__ float g_T[Rr * Dd];         // [4096,1024] gelu activations (concat heads)
__device__ float g_Wt[Dd * Dd];        // blockdiag(w2) @ out_proj
__device__ float g_Wbig[Dd * Dd];      // Wt @ o_proj
__device__ float g_Vcat[Dd * Dd];      // vproj repacked [D, H*HD]
__device__ float g_partial[Bsz * 64 * Dd]; // partial column sums for mean
__device__ float g_c[Bsz * Hh * HDh];  // per-(b,head) folded bias
__device__ float g_vpart[16 * Dd];     // k-split partials for vecmat
__device__ float g_v1[Dd];             // b2cat @ out_proj
__device__ float g_zbias[Dd];          // (b2cat @ out_proj) @ o_proj

// =========================================================================
// tf32 mma.sync GEMM, 128x128x32 tile, 256 thr (8 warps), N and K fixed 1024.
// Fragment-order SMEM, register prefetch, two-stage smem buffer (one
// __syncthreads per k-iter). Optional per-column bias add in epilogue.
// __launch_bounds__(256,2): 2 CTAs/SM (135KB dyn smem total, regs<=128).
// =========================================================================
__device__ __forceinline__ unsigned f2tf32(float v)
{
    unsigned o;
    asm volatile("cvt.rna.tf32.f32 %0, %1;\n" : "=r"(o) : "f"(v));
    return o;
}

__device__ __forceinline__ void mma_tf32(
    float& c0, float& c1, float& c2, float& c3,
    unsigned a0, unsigned a1, unsigned a2, unsigned a3,
    unsigned b0, unsigned b1)
{
    asm volatile(
        "mma.sync.aligned.m16n8k8.row.col.f32.tf32.tf32.f32 "
        "{%0,%1,%2,%3},{%4,%5,%6,%7},{%8,%9},{%0,%1,%2,%3};\n"
        : "+f"(c0), "+f"(c1), "+f"(c2), "+f"(c3)
        : "r"(a0), "r"(a1), "r"(a2), "r"(a3), "r"(b0), "r"(b1));
}

// A: 32 groups (mt 0..7, ks 0..3) of 32 lanes x 4 words, padded 128->132
// B: 64 groups (nt 0..15, ks 0..3) of 32 lanes x 2 words, padded 64->66
#define AGRP 132
#define BGRP 66
#define STGW (32 * AGRP + 64 * BGRP)     // words per stage = 8448
#define GEMM_SMEM_BYTES (2 * STGW * 4)   // 67584

extern __shared__ unsigned dynsmem[];

__global__ __launch_bounds__(256, 2) void gemm_tf32(
    const float* __restrict__ A0, const float* __restrict__ B0,
    float* __restrict__ C0, const float* __restrict__ bias0,
    const float* __restrict__ A1, const float* __restrict__ B1,
    float* __restrict__ C1, const float* __restrict__ bias1,
    int blocks0)
{
    const float* A; const float* Bm; float* C; const float* bias; int rb;
    if ((int)blockIdx.x < blocks0) {
        A = A0; Bm = B0; C = C0; bias = bias0; rb = blockIdx.x;
    } else {
        A = A1; Bm = B1; C = C1; bias = bias1; rb = blockIdx.x - blocks0;
    }

    const int row0 = (rb >> 3) * 128;
    const int col0 = (rb & 7) * 128;

    const int tid    = threadIdx.x;
    const int lane   = tid & 31;
    const int wid    = tid >> 5;
    const int warp_m = wid & 1;          // 64 rows
    const int warp_n = wid >> 1;         // 32 cols

    // ---- precomputed store indices (stage-relative) ----
    float4 pa[4], pb[4];
    const float* Arow[4];
    const float* Brow[4];
    int aidx[4], bidx[4];
#pragma unroll
    for (int i = 0; i < 4; i++) {
        int f = i * 256 + tid;
        int r = f >> 3, q = f & 7;
        Arow[i] = A + (long)(row0 + r) * Dd + q * 4;
        int mt = r >> 4, rr = r & 15;
        int rp = rr & 7, hi = rr >> 3;
        int ks = q >> 1, ch = q & 1;
        aidx[i] = ((mt * 4 + ks) * AGRP) + (rp * 4) * 4 + (hi + 2 * ch);
        int kr = f >> 5, qn = f & 31;
        Brow[i] = Bm + (long)kr * Dd + col0 + qn * 4;
        int nt = qn >> 1, g0 = (qn & 1) * 4;
        int ksb = kr >> 3, slotb = (kr >> 2) & 1;
        bidx[i] = 32 * AGRP + ((nt * 4 + ksb) * BGRP) + (g0 * 4 + (kr & 3)) * 2 + slotb;
    }

    float acc[4][4][4];
#pragma unroll
    for (int i = 0; i < 4; i++)
#pragma unroll
        for (int j = 0; j < 4; j++)
#pragma unroll
            for (int q = 0; q < 4; q++) acc[i][j][q] = 0.0f;

    // prefetch k-tile 0
#pragma unroll
    for (int i = 0; i < 4; i++) { pa[i] = *(const float4*)Arow[i];
                                  pb[i] = *(const float4*)Brow[i]; }

    for (int it = 0; it < 32; it++) {
        unsigned* S = dynsmem + (it & 1) * STGW;

        // ---- store prefetched tile into fragment-order smem (this stage) ----
#pragma unroll
        for (int i = 0; i < 4; i++) {
            S[aidx[i] + 0]  = f2tf32(pa[i].x);
            S[aidx[i] + 4]  = f2tf32(pa[i].y);
            S[aidx[i] + 8]  = f2tf32(pa[i].z);
            S[aidx[i] + 12] = f2tf32(pa[i].w);
            S[bidx[i] + 0]  = f2tf32(pb[i].x);
            S[bidx[i] + 8]  = f2tf32(pb[i].y);
            S[bidx[i] + 16] = f2tf32(pb[i].z);
            S[bidx[i] + 24] = f2tf32(pb[i].w);
        }

        // ---- prefetch next k-tile (A: +k elems; B: +k rows) ----
        if (it < 31) {
            int kn = (it + 1) * 32;
#pragma unroll
            for (int i = 0; i < 4; i++) {
                pa[i] = *(const float4*)(Arow[i] + kn);
                pb[i] = *(const float4*)(Brow[i] + (long)kn * Dd);
            }
        }

        __syncthreads();   // single barrier per iteration (2-stage buffer)

        const unsigned* Sa = S;
#pragma unroll
        for (int ks = 0; ks < 4; ks++) {
            uint4 a[4]; uint2 b[4];
#pragma unroll
            for (int mi = 0; mi < 4; mi++)
                a[mi] = *(const uint4*)&Sa[((warp_m * 4 + mi) * 4 + ks) * AGRP + lane * 4];
#pragma unroll
            for (int ni = 0; ni < 4; ni++)
                b[ni] = *(const uint2*)&Sa[32 * AGRP + ((warp_n * 4 + ni) * 4 + ks) * BGRP + lane * 2];
#pragma unroll
            for (int mi = 0; mi < 4; mi++)
#pragma unroll
                for (int ni = 0; ni < 4; ni++)
                    mma_tf32(acc[mi][ni][0], acc[mi][ni][1],
                             acc[mi][ni][2], acc[mi][ni][3],
                             a[mi].x, a[mi].y, a[mi].z, a[mi].w,
                             b[ni].x, b[ni].y);
        }
        // no trailing sync: next iteration writes the OTHER stage
    }

#pragma unroll
    for (int mi = 0; mi < 4; mi++) {
        int r = row0 + warp_m * 64 + mi * 16 + (lane >> 2);
#pragma unroll
        for (int ni = 0; ni < 4; ni++) {
            int c = col0 + warp_n * 32 + ni * 8 + 2 * (lane & 3);
            float2 v0 = make_float2(acc[mi][ni][0], acc[mi][ni][1]);
            float2 v1 = make_float2(acc[mi][ni][2], acc[mi][ni][3]);
            if (bias) {
                float b0 = bias[c], b1 = bias[c + 1];
                v0.x += b0; v0.y += b1;
                v1.x += b0; v1.y += b1;
            }
            *(float2*)(C + (long)r * Dd + c) = v0;
            *(float2*)(C + (long)(r + 8) * Dd + c) = v1;
        }
    }
}

// -------------------------------------------------------------------------
// Repack vproj [H][D][HD] -> Vcat [D][H*HD]
// -------------------------------------------------------------------------
__global__ __launch_bounds__(256) void repack_vcat(const float* __restrict__ vproj)
{
    int idx = blockIdx.x * 256 + threadIdx.x;   // 0..2^20-1
    int j = idx & 63;
    int k = (idx >> 6) & 1023;
    int h = idx >> 16;
    g_Vcat[(long)k * Dd + h * HDh + j] = vproj[idx];
}

// -------------------------------------------------------------------------
// Wt[h*64+m, :] = sum_j w2[h][m][j] * out_proj[h*64+j, :]
// grid (H, 8): per head, 128-col block. block 256 = 8 rowgroups x 32 colgroups.
// -------------------------------------------------------------------------
__global__ __launch_bounds__(256) void wt_kernel(
    const float* __restrict__ fus_w2, const float* __restrict__ out_proj)
{
    __shared__ float w2s[HDh][HDh];
    __shared__ float ops[HDh][128];

    const int hi = blockIdx.x;
    const int c0 = blockIdx.y * 128;
    const int tid = threadIdx.x;

    const float* w2 = fus_w2 + (long)hi * HDh * HDh;
#pragma unroll
    for (int i = 0; i < 4; i++) {           // 1024 float4 of w2
        int f = i * 256 + tid;
        *(float4*)&w2s[f >> 4][(f & 15) * 4] = *(const float4*)(w2 + f * 4);
    }
#pragma unroll
    for (int i = 0; i < 8; i++) {           // 2048 float4 of OP block
        int f = i * 256 + tid;
        int r = f >> 5, q = f & 31;
        *(float4*)&ops[r][q * 4] =
            *(const float4*)(out_proj + (long)(hi * HDh + r) * Dd + c0 + q * 4);
    }
    __syncthreads();

    const int rg = tid >> 5;                // 0..7 -> rows rg*8..+8
    const int tc = tid & 31;                // cols tc*4..+4
    float accw[8][4];
#pragma unroll
    for (int i = 0; i < 8; i++)
#pragma unroll
        for (int j = 0; j < 4; j++) accw[i][j] = 0.0f;

#pragma unroll 4
    for (int j = 0; j < HDh; j++) {
        float4 ov = *(float4*)&ops[j][tc * 4];
#pragma unroll
        for (int i = 0; i < 8; i++) {
            float w = w2s[rg * 8 + i][j];
            accw[i][0] += w * ov.x;
            accw[i][1] += w * ov.y;
            accw[i][2] += w * ov.z;
            accw[i][3] += w * ov.w;
        }
    }
#pragma unroll
    for (int i = 0; i < 8; i++) {
        float4 v = make_float4(accw[i][0], accw[i][1], accw[i][2], accw[i][3]);
        *(float4*)(g_Wt + (long)(hi * HDh + rg * 8 + i) * Dd + c0 + tc * 4) = v;
    }
}

// -------------------------------------------------------------------------
// Parallel vec @ mat: stage 1 k-split partials, stage 2 fixed-order combine.
// vec [1024], mat [1024,1024]. grid (4,16): 64 blocks, coalesced columns.
// -------------------------------------------------------------------------
__global__ __launch_bounds__(256) void vecmat_partial(
    const float* __restrict__ vec, const float* __restrict__ mat)
{
    int c  = blockIdx.x * 256 + threadIdx.x;
    int kc = blockIdx.y;                      // 16 chunks of 64 rows
    const float* m = mat + (long)kc * 64 * Dd + c;
    const float* v = vec + kc * 64;
    float s = 0.0f;
#pragma unroll 8
    for (int j = 0; j < 64; j++) s += v[j] * m[(long)j * Dd];
    g_vpart[kc * Dd + c] = s;
}

__global__ __launch_bounds__(256) void vecmat_combine(float* __restrict__ outv)
{
    int c = blockIdx.x * 256 + threadIdx.x;
    float s = 0.0f;
#pragma unroll
    for (int k = 0; k < 16; k++) s += g_vpart[k * Dd + c];
    outv[c] = s;
}

// -------------------------------------------------------------------------
// Deterministic mean: stage 1, 32-row partial sums. grid (64, B), block 1024.
// -------------------------------------------------------------------------
__global__ __launch_bounds__(1024) void mean_partial_kernel()
{
    int j  = threadIdx.x;
    int nc = blockIdx.x;
    int b  = blockIdx.y;
    const float* base = g_hf + ((long)b * Nn + nc * 32) * Dd + j;
    float s = 0.0f;
#pragma unroll 8
    for (int n = 0; n < 32; n++) s += base[(long)n * Dd];
    g_partial[((long)b * 64 + nc) * Dd + j] = s;
}

// -------------------------------------------------------------------------
// c[b,h,k] = fus_b1[h,k] + sum_m mean[b,h,m] * (w1[h,64+m,k] + w1[h,128+m,k])
// Block 256 = 64 k-lanes x 4 m-groups; deterministic fixed-order reduction.
// -------------------------------------------------------------------------
__global__ __launch_bounds__(256) void compute_c_kernel(
    const float* __restrict__ fus_w1, const float* __restrict__ fus_b1)
{
    int hi = blockIdx.x, b = blockIdx.y;
    int k = threadIdx.x & 63;
    int g = threadIdx.x >> 6;           // 0..3
    __shared__ float mean_s[HDh];
    __shared__ float part[4][HDh];
    __shared__ float part2[4][HDh];

    float s = 0.0f;
    for (int nc = g * 16; nc < g * 16 + 16; nc++)
        s += g_partial[((long)b * 64 + nc) * Dd + hi * HDh + k];
    part[g][k] = s;
    __syncthreads();
    if (g == 0) {
        float m = ((part[0][k] + part[1][k]) + part[2][k]) + part[3][k];
        mean_s[k] = m * (1.0f / (float)Nn);
    }
    __syncthreads();

    const float* w1 = fus_w1 + (long)hi * 192 * HDh;
    float acc = 0.0f;
#pragma unroll 4
    for (int m = g * 16; m < g * 16 + 16; m++)
        acc += mean_s[m] * (w1[(64 + m) * HDh + k] + w1[(128 + m) * HDh + k]);
    part2[g][k] = acc;
    __syncthreads();
    if (g == 0) {
        float v = fus_b1[hi * HDh + k]
                + ((part2[0][k] + part2[1][k]) + part2[2][k]) + part2[3][k];
        g_c[((long)b * Hh + hi) * HDh + k] = v;
    }
}

__device__ __forceinline__ float gelu_exact(float x)
{
    return 0.5f * x * (1.0f + erff(x * 0.70710678118654752440f));
}

// -------------------------------------------------------------------------
// Fusion layer 1 only: T = gelu(hf_head @ w1[:64] + c[b,h])
// (w2/b2 folded into Wbig/zbias.) Block: 64 rows x 64 cols, 256 threads, 4x4.
// -------------------------------------------------------------------------
__global__ __launch_bounds__(256) void fusion_kernel(
    const float* __restrict__ fus_w1)
{
    __shared__ float hfs[HDh][HDh];
    __shared__ float w1s[HDh][HDh];

    const int hi = blockIdx.y;
    const int r0 = blockIdx.x * 64;
    const int b  = r0 / Nn;
    const int tid = threadIdx.x;
    const int tr = tid >> 4;          // 0..15, 4 rows each
    const int tc = tid & 15;          // 0..15, 4 cols each

    const float* w1 = fus_w1 + (long)hi * 192 * HDh;  // first 64 rows used

#pragma unroll
    for (int i = 0; i < 4; i++) {
        int f = i * 256 + tid;        // float4 index 0..1023
        int m = f >> 4, q = f & 15;
        *(float4*)&w1s[m][q * 4] = *(const float4*)(w1 + m * 64 + q * 4);
        int rl = f >> 4;
        *(float4*)&hfs[rl][q * 4] =
            *(const float4*)(g_hf + (long)(r0 + rl) * Dd + hi * HDh + q * 4);
    }
    float cv[4];
#pragma unroll
    for (int j = 0; j < 4; j++)
        cv[j] = g_c[((long)b * Hh + hi) * HDh + tc * 4 + j];
    __syncthreads();

    float acc[4][4];
#pragma unroll
    for (int i = 0; i < 4; i++)
#pragma unroll
        for (int j = 0; j < 4; j++) acc[i][j] = cv[j];

#pragma unroll 4
    for (int m = 0; m < HDh; m++) {
        float4 wv = *(float4*)&w1s[m][tc * 4];
        float hv[4];
#pragma unroll
        for (int i = 0; i < 4; i++) hv[i] = hfs[tr * 4 + i][m];
#pragma unroll
        for (int i = 0; i < 4; i++) {
            acc[i][0] += hv[i] * wv.x;
            acc[i][1] += hv[i] * wv.y;
            acc[i][2] += hv[i] * wv.z;
            acc[i][3] += hv[i] * wv.w;
        }
    }
#pragma unroll
    for (int i = 0; i < 4; i++) {
        float4 v = make_float4(gelu_exact(acc[i][0]), gelu_exact(acc[i][1]),
                               gelu_exact(acc[i][2]), gelu_exact(acc[i][3]));
        *(float4*)(g_T + (long)(r0 + tr * 4 + i) * Dd + hi * HDh + tc * 4) = v;
    }
}

// -------------------------------------------------------------------------
// Tail outputs (constants), only if the output buffer carries them.
// -------------------------------------------------------------------------
__global__ void tail_kernel(float* __restrict__ out, int out_size)
{
    const int base = Rr * Dd;
    int i = blockIdx.x * blockDim.x + threadIdx.x;
    if (out_size >= base + 2 * Rr) {
        float strength = 1.0f - logf(1.0f / (float)Nn + 1e-8f);
        if (i < Rr)            out[base + i] = 1023.0f;
        else if (i < 2 * Rr)   out[base + i] = strength;
    }
}

// -------------------------------------------------------------------------
extern "C" void kernel_launch(void* const* d_in, const int* in_sizes, int n_in,
                              void* d_out, int out_size)
{
    const float* h         = (const float*)d_in[0];
    // d_in[1..8]: fe/be scorer weights -> provably dead (uniform softmax)
    const float* vproj_w   = (const float*)d_in[9];
    const float* fus_w1    = (const float*)d_in[10];
    const float* fus_b1    = (const float*)d_in[11];
    const float* fus_w2    = (const float*)d_in[12];
    const float* fus_b2    = (const float*)d_in[13];
    const float* out_proj  = (const float*)d_in[14];
    const float* o_proj    = (const float*)d_in[15];
    float* z = (float*)d_out;

    float *hf_p, *T_p, *Wt_p, *Wbig_p, *vcat_p, *v1_p, *zb_p;
    cudaGetSymbolAddress((void**)&hf_p,   g_hf);
    cudaGetSymbolAddress((void**)&T_p,    g_T);
    cudaGetSymbolAddress((void**)&Wt_p,   g_Wt);
    cudaGetSymbolAddress((void**)&Wbig_p, g_Wbig);
    cudaGetSymbolAddress((void**)&vcat_p, g_Vcat);
    cudaGetSymbolAddress((void**)&v1_p,   g_v1);
    cudaGetSymbolAddress((void**)&zb_p,   g_zbias);

    static int smem_set = 0;
    if (!smem_set) {
        cudaFuncSetAttribute(gemm_tf32,
                             cudaFuncAttributeMaxDynamicSharedMemorySize,
                             GEMM_SMEM_BYTES);
        smem_set = 1;
    }

    // 0) small precomputes: Vcat repack, Wt = BD(w2)@out_proj, zbias chain
    repack_vcat<<<(Dd * Dd) / 256, 256>>>(vproj_w);
    {
        dim3 gw(Hh, 8);
        wt_kernel<<<gw, 256>>>(fus_w2, out_proj);
    }
    {
        dim3 gv(4, 16);
        vecmat_partial<<<gv, 256>>>(fus_b2, out_proj);   // fus_b2 is [H*HD]=1024
        vecmat_combine<<<4, 256>>>(v1_p);
        vecmat_partial<<<gv, 256>>>(v1_p, o_proj);
        vecmat_combine<<<4, 256>>>(zb_p);
    }

    // 1+2) hf = h @ Vcat  AND  Wbig = Wt @ o_proj, one packed launch
    gemm_tf32<<<320, 256, GEMM_SMEM_BYTES>>>(
        h, vcat_p, hf_p, (const float*)0,
        Wt_p, o_proj, Wbig_p, (const float*)0, 256);

    // 3) deterministic mean over sequence + folded bias c
    {
        dim3 grid(64, Bsz);
        mean_partial_kernel<<<grid, 1024>>>();
        dim3 gridc(Hh, Bsz);
        compute_c_kernel<<<gridc, 256>>>(fus_w1, fus_b1);
    }
    // 4) fusion layer 1 -> T
    {
        dim3 grid(Rr / 64, Hh);
        fusion_kernel<<<grid, 256>>>(fus_w1);
    }
    // 5) z = T @ Wbig + zbias   (writes directly into d_out)
    gemm_tf32<<<256, 256, GEMM_SMEM_BYTES>>>(
        T_p, Wbig_p, z, zb_p,
        T_p, Wbig_p, z, zb_p, 256);

    // 6) constant tail outputs
    tail_kernel<<<32, 256>>>(z, out_size);
}

// round 11
// speedup vs baseline: 1.3777x; 1.0431x over previous
#include <cuda_runtime.h>
#include <math.h>

// Problem constants
#define Bsz 2
#define Nn  2048
#define Dd  1024
#define Hh  16
#define HDh 64
#define Rr  (Bsz * Nn)          // 4096 rows total

// Scratch (no allocation allowed -> device globals)
__device__ float g_hf[Rr * Dd];        // [4096,1024] per-head value features
__device__ float g_multi[Rr * Dd];     // [4096,1024] fused head outputs
__device__ float g_W12[Dd * Dd];       // out_proj @ o_proj
__device__ float g_Vcat[Dd * Dd];      // vproj repacked [D, H*HD]
__device__ float g_partial[Bsz * 64 * Dd]; // partial column sums for mean
__device__ float g_c[Bsz * Hh * HDh];  // per-(b,head) folded bias

// =========================================================================
// tf32 mma.sync GEMM, 128x128x32 tile, 256 thr (8 warps), N and K fixed 1024.
// Fragment-order SMEM, register prefetch, two-stage smem buffer (one
// __syncthreads per k-iter). Loader state = 2 base pointers + immediate
// offsets (A row step 32*Dd, B row step 8*Dd, aidx step 8*AGRP, bidx step
// BGRP) so the whole kernel fits in 128 regs -> __launch_bounds__(256,2)
// gives 2 CTAs/SM WITHOUT spills (135KB dyn smem total < 228KB).
// =========================================================================
__device__ __forceinline__ unsigned f2tf32(float v)
{
    unsigned o;
    asm volatile("cvt.rna.tf32.f32 %0, %1;\n" : "=r"(o) : "f"(v));
    return o;
}

__device__ __forceinline__ void mma_tf32(
    float& c0, float& c1, float& c2, float& c3,
    unsigned a0, unsigned a1, unsigned a2, unsigned a3,
    unsigned b0, unsigned b1)
{
    asm volatile(
        "mma.sync.aligned.m16n8k8.row.col.f32.tf32.tf32.f32 "
        "{%0,%1,%2,%3},{%4,%5,%6,%7},{%8,%9},{%0,%1,%2,%3};\n"
        : "+f"(c0), "+f"(c1), "+f"(c2), "+f"(c3)
        : "r"(a0), "r"(a1), "r"(a2), "r"(a3), "r"(b0), "r"(b1));
}

// A: 32 groups (mt 0..7, ks 0..3) of 32 lanes x 4 words, padded 128->132
// B: 64 groups (nt 0..15, ks 0..3) of 32 lanes x 2 words, padded 64->66
#define AGRP 132
#define BGRP 66
#define STGW (32 * AGRP + 64 * BGRP)     // words per stage = 8448
#define GEMM_SMEM_BYTES (2 * STGW * 4)   // 67584

extern __shared__ unsigned dynsmem[];

__global__ __launch_bounds__(256, 2) void gemm_tf32(
    const float* __restrict__ A0, const float* __restrict__ B0,
    float* __restrict__ C0,
    const float* __restrict__ A1, const float* __restrict__ B1,
    float* __restrict__ C1, int blocks0)
{
    const float* A; const float* Bm; float* C; int rb;
    if ((int)blockIdx.x < blocks0) { A = A0; Bm = B0; C = C0; rb = blockIdx.x; }
    else { A = A1; Bm = B1; C = C1; rb = blockIdx.x - blocks0; }

    const int row0 = (rb >> 3) * 128;
    const int col0 = (rb & 7) * 128;

    const int tid    = threadIdx.x;
    const int lane   = tid & 31;
    const int wid    = tid >> 5;
    const int warp_m = wid & 1;          // 64 rows
    const int warp_n = wid >> 1;         // 32 cols

    // ---- loader bases (i-th chunk = base + compile-time offset) ----
    // A: f = i*256+tid -> r = tid>>3 + 32*i, q = tid&7
    // B: f = i*256+tid -> kr = tid>>5 + 8*i, qn = tid&31
    const int r  = tid >> 3, q  = tid & 7;
    const int kr = tid >> 5, qn = tid & 31;

    const float* Abase = A  + (long)(row0 + r) * Dd + q * 4;
    const float* Bbase = Bm + (long)kr * Dd + col0 + qn * 4;

    const int mt = r >> 4, rr = r & 15;
    const int rp = rr & 7, hb = rr >> 3;
    const int ks0 = q >> 1, ch = q & 1;
    const int aidx0 = (mt * 4 + ks0) * AGRP + rp * 16 + (hb + 2 * ch);
    // per i: aidx += 8*AGRP   (r += 32 -> mt += 2)

    const int nt = qn >> 1, g0 = (qn & 1) * 4;
    const int slotb = (kr >> 2) & 1;
    const int bidx0 = 32 * AGRP + (nt * 4) * BGRP + (g0 * 4 + (kr & 3)) * 2 + slotb;
    // per i: bidx += BGRP     (kr += 8 -> ksb += 1)

    float acc[4][4][4];
#pragma unroll
    for (int i = 0; i < 4; i++)
#pragma unroll
        for (int j = 0; j < 4; j++)
#pragma unroll
            for (int qq = 0; qq < 4; qq++) acc[i][j][qq] = 0.0f;

    float4 pa[4], pb[4];
    // prefetch k-tile 0
#pragma unroll
    for (int i = 0; i < 4; i++) {
        pa[i] = *(const float4*)(Abase + (long)i * 32 * Dd);
        pb[i] = *(const float4*)(Bbase + (long)i * 8 * Dd);
    }

    for (int it = 0; it < 32; it++) {
        unsigned* S = dynsmem + (it & 1) * STGW;

        // ---- store prefetched tile into fragment-order smem (this stage) ----
#pragma unroll
        for (int i = 0; i < 4; i++) {
            const int ai = aidx0 + i * 8 * AGRP;
            S[ai + 0]  = f2tf32(pa[i].x);
            S[ai + 4]  = f2tf32(pa[i].y);
            S[ai + 8]  = f2tf32(pa[i].z);
            S[ai + 12] = f2tf32(pa[i].w);
            const int bi = bidx0 + i * BGRP;
            S[bi + 0]  = f2tf32(pb[i].x);
            S[bi + 8]  = f2tf32(pb[i].y);
            S[bi + 16] = f2tf32(pb[i].z);
            S[bi + 24] = f2tf32(pb[i].w);
        }

        // ---- prefetch next k-tile (A: +k elems along row; B: +k rows) ----
        if (it < 31) {
            const int kn = (it + 1) * 32;
#pragma unroll
            for (int i = 0; i < 4; i++) {
                pa[i] = *(const float4*)(Abase + kn + (long)i * 32 * Dd);
                pb[i] = *(const float4*)(Bbase + (long)(kn + i * 8) * Dd);
            }
        }

        __syncthreads();   // single barrier per iteration (2-stage buffer)

        const unsigned* Sa = S;
#pragma unroll
        for (int ks = 0; ks < 4; ks++) {
            uint4 a[4]; uint2 b[4];
#pragma unroll
            for (int mi = 0; mi < 4; mi++)
                a[mi] = *(const uint4*)&Sa[((warp_m * 4 + mi) * 4 + ks) * AGRP + lane * 4];
#pragma unroll
            for (int ni = 0; ni < 4; ni++)
                b[ni] = *(const uint2*)&Sa[32 * AGRP + ((warp_n * 4 + ni) * 4 + ks) * BGRP + lane * 2];
#pragma unroll
            for (int mi = 0; mi < 4; mi++)
#pragma unroll
                for (int ni = 0; ni < 4; ni++)
                    mma_tf32(acc[mi][ni][0], acc[mi][ni][1],
                             acc[mi][ni][2], acc[mi][ni][3],
                             a[mi].x, a[mi].y, a[mi].z, a[mi].w,
                             b[ni].x, b[ni].y);
        }
        // no trailing sync: next iteration writes the OTHER stage
    }

#pragma unroll
    for (int mi = 0; mi < 4; mi++) {
        int rro = row0 + warp_m * 64 + mi * 16 + (lane >> 2);
#pragma unroll
        for (int ni = 0; ni < 4; ni++) {
            int c = col0 + warp_n * 32 + ni * 8 + 2 * (lane & 3);
            *(float2*)(C + (long)rro * Dd + c) =
                make_float2(acc[mi][ni][0], acc[mi][ni][1]);
            *(float2*)(C + (long)(rro + 8) * Dd + c) =
                make_float2(acc[mi][ni][2], acc[mi][ni][3]);
        }
    }
}

// -------------------------------------------------------------------------
// Repack vproj [H][D][HD] -> Vcat [D][H*HD]
// -------------------------------------------------------------------------
__global__ __launch_bounds__(256) void repack_vcat(const float* __restrict__ vproj)
{
    int idx = blockIdx.x * 256 + threadIdx.x;   // 0..2^20-1
    int j = idx & 63;
    int k = (idx >> 6) & 1023;
    int h = idx >> 16;
    g_Vcat[(long)k * Dd + h * HDh + j] = vproj[idx];
}

// -------------------------------------------------------------------------
// Deterministic mean: stage 1, 32-row partial sums. grid (64, B), block 1024.
// -------------------------------------------------------------------------
__global__ __launch_bounds__(1024) void mean_partial_kernel()
{
    int j  = threadIdx.x;
    int nc = blockIdx.x;
    int b  = blockIdx.y;
    const float* base = g_hf + ((long)b * Nn + nc * 32) * Dd + j;
    float s = 0.0f;
#pragma unroll 8
    for (int n = 0; n < 32; n++) s += base[(long)n * Dd];
    g_partial[((long)b * 64 + nc) * Dd + j] = s;
}

// -------------------------------------------------------------------------
// c[b,h,k] = fus_b1[h,k] + sum_m mean[b,h,m] * (w1[h,64+m,k] + w1[h,128+m,k])
// Block 256 = 64 k-lanes x 4 m-groups; deterministic fixed-order reduction.
// -------------------------------------------------------------------------
__global__ __launch_bounds__(256) void compute_c_kernel(
    const float* __restrict__ fus_w1, const float* __restrict__ fus_b1)
{
    int hi = blockIdx.x, b = blockIdx.y;
    int k = threadIdx.x & 63;
    int g = threadIdx.x >> 6;           // 0..3
    __shared__ float mean_s[HDh];
    __shared__ float part[4][HDh];
    __shared__ float part2[4][HDh];

    float s = 0.0f;
    for (int nc = g * 16; nc < g * 16 + 16; nc++)
        s += g_partial[((long)b * 64 + nc) * Dd + hi * HDh + k];
    part[g][k] = s;
    __syncthreads();
    if (g == 0) {
        float m = ((part[0][k] + part[1][k]) + part[2][k]) + part[3][k];
        mean_s[k] = m * (1.0f / (float)Nn);
    }
    __syncthreads();

    const float* w1 = fus_w1 + (long)hi * 192 * HDh;
    float acc = 0.0f;
#pragma unroll 4
    for (int m = g * 16; m < g * 16 + 16; m++)
        acc += mean_s[m] * (w1[(64 + m) * HDh + k] + w1[(128 + m) * HDh + k]);
    part2[g][k] = acc;
    __syncthreads();
    if (g == 0) {
        float v = fus_b1[hi * HDh + k]
                + ((part2[0][k] + part2[1][k]) + part2[2][k]) + part2[3][k];
        g_c[((long)b * Hh + hi) * HDh + k] = v;
    }
}

__device__ __forceinline__ float gelu_exact(float x)
{
    return 0.5f * x * (1.0f + erff(x * 0.70710678118654752440f));
}

// -------------------------------------------------------------------------
// Fused per-head relation MLP, register-tiled 4x4 (64 rows x 64 cols/block):
//   t  = gelu(hf_head @ w1[:64] + c[b,h]);  ho = t @ w2 + b2  -> multi
// -------------------------------------------------------------------------
__global__ __launch_bounds__(256) void fusion_kernel(
    const float* __restrict__ fus_w1, const float* __restrict__ fus_w2,
    const float* __restrict__ fus_b2)
{
    __shared__ float hfs[HDh][HDh];
    __shared__ float w1s[HDh][HDh];   // reused as t after first layer
    __shared__ float w2s[HDh][HDh];

    const int hi = blockIdx.y;
    const int r0 = blockIdx.x * 64;
    const int b  = r0 / Nn;
    const int tid = threadIdx.x;
    const int tr = tid >> 4;          // 0..15, 4 rows each
    const int tc = tid & 15;          // 0..15, 4 cols each

    const float* w1 = fus_w1 + (long)hi * 192 * HDh;  // first 64 rows used
    const float* w2 = fus_w2 + (long)hi * HDh * HDh;

#pragma unroll
    for (int i = 0; i < 4; i++) {
        int f = i * 256 + tid;        // float4 index 0..1023
        int m = f >> 4, qq = f & 15;
        *(float4*)&w1s[m][qq * 4] = *(const float4*)(w1 + m * 64 + qq * 4);
        *(float4*)&w2s[m][qq * 4] = *(const float4*)(w2 + m * 64 + qq * 4);
        int rl = f >> 4;
        *(float4*)&hfs[rl][qq * 4] =
            *(const float4*)(g_hf + (long)(r0 + rl) * Dd + hi * HDh + qq * 4);
    }
    float cv[4], b2v[4];
#pragma unroll
    for (int j = 0; j < 4; j++) {
        cv[j]  = g_c[((long)b * Hh + hi) * HDh + tc * 4 + j];
        b2v[j] = fus_b2[hi * HDh + tc * 4 + j];
    }
    __syncthreads();

    float acc[4][4];
#pragma unroll
    for (int i = 0; i < 4; i++)
#pragma unroll
        for (int j = 0; j < 4; j++) acc[i][j] = cv[j];

#pragma unroll 4
    for (int m = 0; m < HDh; m++) {
        float4 wv = *(float4*)&w1s[m][tc * 4];
        float hv[4];
#pragma unroll
        for (int i = 0; i < 4; i++) hv[i] = hfs[tr * 4 + i][m];
#pragma unroll
        for (int i = 0; i < 4; i++) {
            acc[i][0] += hv[i] * wv.x;
            acc[i][1] += hv[i] * wv.y;
            acc[i][2] += hv[i] * wv.z;
            acc[i][3] += hv[i] * wv.w;
        }
    }
    __syncthreads();   // everyone done reading w1s
#pragma unroll
    for (int i = 0; i < 4; i++)
#pragma unroll
        for (int j = 0; j < 4; j++)
            w1s[tr * 4 + i][tc * 4 + j] = gelu_exact(acc[i][j]);
    __syncthreads();

    float acc2[4][4];
#pragma unroll
    for (int i = 0; i < 4; i++)
#pragma unroll
        for (int j = 0; j < 4; j++) acc2[i][j] = b2v[j];

#pragma unroll 4
    for (int m = 0; m < HDh; m++) {
        float4 wv = *(float4*)&w2s[m][tc * 4];
        float tv[4];
#pragma unroll
        for (int i = 0; i < 4; i++) tv[i] = w1s[tr * 4 + i][m];
#pragma unroll
        for (int i = 0; i < 4; i++) {
            acc2[i][0] += tv[i] * wv.x;
            acc2[i][1] += tv[i] * wv.y;
            acc2[i][2] += tv[i] * wv.z;
            acc2[i][3] += tv[i] * wv.w;
        }
    }
#pragma unroll
    for (int i = 0; i < 4; i++) {
        float4 v = make_float4(acc2[i][0], acc2[i][1], acc2[i][2], acc2[i][3]);
        *(float4*)(g_multi + (long)(r0 + tr * 4 + i) * Dd + hi * HDh + tc * 4) = v;
    }
}

// -------------------------------------------------------------------------
// Tail outputs (constants), only if the output buffer carries them.
// -------------------------------------------------------------------------
__global__ void tail_kernel(float* __restrict__ out, int out_size)
{
    const int base = Rr * Dd;
    int i = blockIdx.x * blockDim.x + threadIdx.x;
    if (out_size >= base + 2 * Rr) {
        float strength = 1.0f - logf(1.0f / (float)Nn + 1e-8f);
        if (i < Rr)            out[base + i] = 1023.0f;
        else if (i < 2 * Rr)   out[base + i] = strength;
    }
}

// -------------------------------------------------------------------------
extern "C" void kernel_launch(void* const* d_in, const int* in_sizes, int n_in,
                              void* d_out, int out_size)
{
    const float* h         = (const float*)d_in[0];
    // d_in[1..8]: fe/be scorer weights -> provably dead (uniform softmax)
    const float* vproj_w   = (const float*)d_in[9];
    const float* fus_w1    = (const float*)d_in[10];
    const float* fus_b1    = (const float*)d_in[11];
    const float* fus_w2    = (const float*)d_in[12];
    const float* fus_b2    = (const float*)d_in[13];
    const float* out_proj  = (const float*)d_in[14];
    const float* o_proj    = (const float*)d_in[15];
    float* z = (float*)d_out;

    float *hf_p, *multi_p, *W12_p, *vcat_p;
    cudaGetSymbolAddress((void**)&hf_p,    g_hf);
    cudaGetSymbolAddress((void**)&multi_p, g_multi);
    cudaGetSymbolAddress((void**)&W12_p,   g_W12);
    cudaGetSymbolAddress((void**)&vcat_p,  g_Vcat);

    static int smem_set = 0;
    if (!smem_set) {
        cudaFuncSetAttribute(gemm_tf32,
                             cudaFuncAttributeMaxDynamicSharedMemorySize,
                             GEMM_SMEM_BYTES);
        smem_set = 1;
    }

    // 0) repack vproj into contiguous [D, D]
    repack_vcat<<<(Dd * Dd) / 256, 256>>>(vproj_w);

    // 1+2) hf = h @ Vcat  AND  W12 = out_proj @ o_proj, one packed launch
    //      256 + 64 = 320 blocks; occ 2 -> 1.08 waves on 148 SMs
    gemm_tf32<<<320, 256, GEMM_SMEM_BYTES>>>(h, vcat_p, hf_p,
                                             out_proj, o_proj, W12_p, 256);

    // 3) deterministic mean over sequence + folded bias c
    {
        dim3 grid(64, Bsz);
        mean_partial_kernel<<<grid, 1024>>>();
        dim3 gridc(Hh, Bsz);
        compute_c_kernel<<<gridc, 256>>>(fus_w1, fus_b1);
    }
    // 4) fused per-head relation MLP -> multi
    {
        dim3 grid(Rr / 64, Hh);
        fusion_kernel<<<grid, 256>>>(fus_w1, fus_w2, fus_b2);
    }
    // 5) z = multi @ W12   (writes directly into d_out)
    gemm_tf32<<<256, 256, GEMM_SMEM_BYTES>>>(multi_p, W12_p, z,
                                             multi_p, W12_p, z, 256);

    // 6) constant tail outputs
    tail_kernel<<<32, 256>>>(z, out_size);
}

// round 17
// speedup vs baseline: 1.3792x; 1.0011x over previous
#include <cuda_runtime.h>
#include <math.h>

// Problem constants
#define Bsz 2
#define Nn  2048
#define Dd  1024
#define Hh  16
#define HDh 64
#define Rr  (Bsz * Nn)          // 4096 rows total

// Scratch (no allocation allowed -> device globals)
__device__ float g_T[Rr * Dd];         // gelu activations (GEMM-A output)
__device__ float g_U[Dd * Dd];         // per-head vproj @ w1[:64], side by side
__device__ float g_Wt[Dd * Dd];        // blockdiag(w2) @ out_proj
__device__ float g_Wbig[Dd * Dd];      // Wt @ o_proj
__device__ float g_partial[Bsz * 64 * Dd]; // h column partial sums
__device__ float g_meanH[Bsz * Dd];    // mean over rows of h
__device__ float g_c[Bsz * Dd];        // folded layer-1 bias, [B][H*HD]
__device__ float g_vpart[16 * Dd];     // k-split partials for vecmat
__device__ float g_v1[Dd];             // b2cat @ out_proj
__device__ float g_zbias[Dd];          // (b2cat @ out_proj) @ o_proj

__device__ __forceinline__ float gelu_exact(float x)
{
    return 0.5f * x * (1.0f + erff(x * 0.70710678118654752440f));
}

// =========================================================================
// tf32 mma.sync GEMM, 128x128x32 tile, 256 thr (8 warps), N and K fixed 1024.
// Fragment-order SMEM, register prefetch, two-stage smem buffer (one
// __syncthreads per k-iter). Epilogue modes: 0 = plain store,
// 1 = gelu(acc + c[b, col]) (b = row0>>11), 2 = acc + bias[col].
// Packed dual-operand launch (blocks0 selects operand set).
// =========================================================================
__device__ __forceinline__ unsigned f2tf32(float v)
{
    unsigned o;
    asm volatile("cvt.rna.tf32.f32 %0, %1;\n" : "=r"(o) : "f"(v));
    return o;
}

__device__ __forceinline__ void mma_tf32(
    float& c0, float& c1, float& c2, float& c3,
    unsigned a0, unsigned a1, unsigned a2, unsigned a3,
    unsigned b0, unsigned b1)
{
    asm volatile(
        "mma.sync.aligned.m16n8k8.row.col.f32.tf32.tf32.f32 "
        "{%0,%1,%2,%3},{%4,%5,%6,%7},{%8,%9},{%0,%1,%2,%3};\n"
        : "+f"(c0), "+f"(c1), "+f"(c2), "+f"(c3)
        : "r"(a0), "r"(a1), "r"(a2), "r"(a3), "r"(b0), "r"(b1));
}

// A: 32 groups (mt 0..7, ks 0..3) of 32 lanes x 4 words, padded 128->132
// B: 64 groups (nt 0..15, ks 0..3) of 32 lanes x 2 words, padded 64->66
#define AGRP 132
#define BGRP 66
#define STGW (32 * AGRP + 64 * BGRP)     // words per stage = 8448
#define GEMM_SMEM_BYTES (2 * STGW * 4)   // 67584

extern __shared__ unsigned dynsmem[];

__global__ __launch_bounds__(256, 2) void gemm_tf32(
    const float* __restrict__ A0, const float* __restrict__ B0,
    float* __restrict__ C0, const float* __restrict__ E0, int m0,
    const float* __restrict__ A1, const float* __restrict__ B1,
    float* __restrict__ C1, const float* __restrict__ E1, int m1,
    int blocks0)
{
    const float* A; const float* Bm; float* C; const float* E; int mode; int rb;
    if ((int)blockIdx.x < blocks0) {
        A = A0; Bm = B0; C = C0; E = E0; mode = m0; rb = blockIdx.x;
    } else {
        A = A1; Bm = B1; C = C1; E = E1; mode = m1; rb = blockIdx.x - blocks0;
    }

    const int row0 = (rb >> 3) * 128;
    const int col0 = (rb & 7) * 128;

    const int tid    = threadIdx.x;
    const int lane   = tid & 31;
    const int wid    = tid >> 5;
    const int warp_m = wid & 1;          // 64 rows
    const int warp_n = wid >> 1;         // 32 cols

    // loader bases: chunk i = base + compile-time offset
    const int r  = tid >> 3, q  = tid & 7;
    const int kr = tid >> 5, qn = tid & 31;

    const float* Abase = A  + (long)(row0 + r) * Dd + q * 4;
    const float* Bbase = Bm + (long)kr * Dd + col0 + qn * 4;

    const int mt = r >> 4, rr = r & 15;
    const int rp = rr & 7, hb = rr >> 3;
    const int ks0 = q >> 1, ch = q & 1;
    const int aidx0 = (mt * 4 + ks0) * AGRP + rp * 16 + (hb + 2 * ch);
    const int nt = qn >> 1, g0 = (qn & 1) * 4;
    const int slotb = (kr >> 2) & 1;
    const int bidx0 = 32 * AGRP + (nt * 4) * BGRP + (g0 * 4 + (kr & 3)) * 2 + slotb;

    float acc[4][4][4];
#pragma unroll
    for (int i = 0; i < 4; i++)
#pragma unroll
        for (int j = 0; j < 4; j++)
#pragma unroll
            for (int qq = 0; qq < 4; qq++) acc[i][j][qq] = 0.0f;

    float4 pa[4], pb[4];
#pragma unroll
    for (int i = 0; i < 4; i++) {
        pa[i] = *(const float4*)(Abase + (long)i * 32 * Dd);
        pb[i] = *(const float4*)(Bbase + (long)i * 8 * Dd);
    }

    for (int it = 0; it < 32; it++) {
        unsigned* S = dynsmem + (it & 1) * STGW;

#pragma unroll
        for (int i = 0; i < 4; i++) {
            const int ai = aidx0 + i * 8 * AGRP;
            S[ai + 0]  = f2tf32(pa[i].x);
            S[ai + 4]  = f2tf32(pa[i].y);
            S[ai + 8]  = f2tf32(pa[i].z);
            S[ai + 12] = f2tf32(pa[i].w);
            const int bi = bidx0 + i * BGRP;
            S[bi + 0]  = f2tf32(pb[i].x);
            S[bi + 8]  = f2tf32(pb[i].y);
            S[bi + 16] = f2tf32(pb[i].z);
            S[bi + 24] = f2tf32(pb[i].w);
        }

        if (it < 31) {
            const int kn = (it + 1) * 32;
#pragma unroll
            for (int i = 0; i < 4; i++) {
                pa[i] = *(const float4*)(Abase + kn + (long)i * 32 * Dd);
                pb[i] = *(const float4*)(Bbase + (long)(kn + i * 8) * Dd);
            }
        }

        __syncthreads();   // single barrier per iteration (2-stage buffer)

        const unsigned* Sa = S;
#pragma unroll
        for (int ks = 0; ks < 4; ks++) {
            uint4 a[4]; uint2 b[4];
#pragma unroll
            for (int mi = 0; mi < 4; mi++)
                a[mi] = *(const uint4*)&Sa[((warp_m * 4 + mi) * 4 + ks) * AGRP + lane * 4];
#pragma unroll
            for (int ni = 0; ni < 4; ni++)
                b[ni] = *(const uint2*)&Sa[32 * AGRP + ((warp_n * 4 + ni) * 4 + ks) * BGRP + lane * 2];
#pragma unroll
            for (int mi = 0; mi < 4; mi++)
#pragma unroll
                for (int ni = 0; ni < 4; ni++)
                    mma_tf32(acc[mi][ni][0], acc[mi][ni][1],
                             acc[mi][ni][2], acc[mi][ni][3],
                             a[mi].x, a[mi].y, a[mi].z, a[mi].w,
                             b[ni].x, b[ni].y);
        }
    }

    // epilogue: whole 128-row tile shares one batch index (2048-aligned)
    const float* cb = E ? (mode == 1 ? E + (long)(row0 >> 11) * Dd : E) : 0;
#pragma unroll
    for (int mi = 0; mi < 4; mi++) {
        int rro = row0 + warp_m * 64 + mi * 16 + (lane >> 2);
#pragma unroll
        for (int ni = 0; ni < 4; ni++) {
            int cc = col0 + warp_n * 32 + ni * 8 + 2 * (lane & 3);
            float o0 = acc[mi][ni][0], o1 = acc[mi][ni][1];
            float o2 = acc[mi][ni][2], o3 = acc[mi][ni][3];
            if (mode == 1) {
                float e0 = cb[cc], e1 = cb[cc + 1];
                o0 = gelu_exact(o0 + e0); o1 = gelu_exact(o1 + e1);
                o2 = gelu_exact(o2 + e0); o3 = gelu_exact(o3 + e1);
            } else if (mode == 2) {
                float e0 = cb[cc], e1 = cb[cc + 1];
                o0 += e0; o1 += e1; o2 += e0; o3 += e1;
            }
            *(float2*)(C + (long)rro * Dd + cc)       = make_float2(o0, o1);
            *(float2*)(C + (long)(rro + 8) * Dd + cc) = make_float2(o2, o3);
        }
    }
}

// -------------------------------------------------------------------------
// mean over rows of h: stage 1 partials (32 rows/block), stage 2 combine.
// -------------------------------------------------------------------------
__global__ __launch_bounds__(1024) void mean_partial_kernel(const float* __restrict__ h)
{
    int j  = threadIdx.x;
    int nc = blockIdx.x;
    int b  = blockIdx.y;
    const float* base = h + ((long)b * Nn + nc * 32) * Dd + j;
    float s = 0.0f;
#pragma unroll 8
    for (int n = 0; n < 32; n++) s += base[(long)n * Dd];
    g_partial[((long)b * 64 + nc) * Dd + j] = s;
}

__global__ __launch_bounds__(1024) void mean_combine_kernel()
{
    int j = threadIdx.x;
    int b = blockIdx.x;
    float s = 0.0f;
#pragma unroll
    for (int nc = 0; nc < 64; nc++)
        s += g_partial[((long)b * 64 + nc) * Dd + j];
    g_meanH[b * Dd + j] = s * (1.0f / (float)Nn);
}

// -------------------------------------------------------------------------
// c[b, h*64+k] = b1[h,k] + sum_m meanv[m] * (w1[h,64+m,k] + w1[h,128+m,k]),
// meanv[m] = sum_k meanH[b,k] * vproj[h,k,m].
// grid (H, B), block 256 = 64 m-lanes x 4 k-chunks; fixed-order reduce.
// -------------------------------------------------------------------------
__global__ __launch_bounds__(256) void compute_c_kernel(
    const float* __restrict__ vproj, const float* __restrict__ fus_w1,
    const float* __restrict__ fus_b1)
{
    int hi = blockIdx.x, b = blockIdx.y;
    int m = threadIdx.x & 63;
    int g = threadIdx.x >> 6;           // 0..3
    __shared__ float part[4][HDh];
    __shared__ float meanv[HDh];
    __shared__ float part2[4][HDh];

    const float* vp = vproj + (long)hi * Dd * HDh;
    const float* mh = g_meanH + b * Dd;
    float s = 0.0f;
    for (int k = g * 256; k < g * 256 + 256; k++)
        s += mh[k] * vp[(long)k * HDh + m];
    part[g][m] = s;
    __syncthreads();
    if (g == 0)
        meanv[m] = ((part[0][m] + part[1][m]) + part[2][m]) + part[3][m];
    __syncthreads();

    const float* w1 = fus_w1 + (long)hi * 192 * HDh;
    float acc = 0.0f;
#pragma unroll 4
    for (int mm = g * 16; mm < g * 16 + 16; mm++)
        acc += meanv[mm] * (w1[(64 + mm) * HDh + m] + w1[(128 + mm) * HDh + m]);
    part2[g][m] = acc;
    __syncthreads();
    if (g == 0) {
        float v = fus_b1[hi * HDh + m]
                + ((part2[0][m] + part2[1][m]) + part2[2][m]) + part2[3][m];
        g_c[b * Dd + hi * HDh + m] = v;
    }
}

// -------------------------------------------------------------------------
// U[k][h*64+j] = sum_m vproj[h][k][m] * w1[h][m][j]   (layer-1 weight fold)
// grid (H, 8): 128 k-rows per block. block 256: (kr = tid>>1, half = tid&1).
// -------------------------------------------------------------------------
__global__ __launch_bounds__(256) void u_kernel(
    const float* __restrict__ vproj, const float* __restrict__ fus_w1)
{
    __shared__ float w1s[HDh][HDh];

    const int hi = blockIdx.x;
    const int k0 = blockIdx.y * 128;
    const int tid = threadIdx.x;

    const float* w1 = fus_w1 + (long)hi * 192 * HDh;   // rows 0..63
#pragma unroll
    for (int i = 0; i < 4; i++) {
        int f = i * 256 + tid;                          // float4 idx 0..1023
        *(float4*)&w1s[f >> 4][(f & 15) * 4] = *(const float4*)(w1 + f * 4);
    }
    __syncthreads();

    const int krr = tid >> 1;
    const int half = (tid & 1) * 32;
    const float* vp = vproj + (long)hi * Dd * HDh + (long)(k0 + krr) * HDh;

    float acc[32];
#pragma unroll
    for (int j = 0; j < 32; j++) acc[j] = 0.0f;
#pragma unroll 8
    for (int m = 0; m < HDh; m++) {
        float v = vp[m];
#pragma unroll
        for (int j = 0; j < 32; j++) acc[j] += v * w1s[m][half + j];
    }
    float* out = g_U + (long)(k0 + krr) * Dd + hi * HDh + half;
#pragma unroll
    for (int j = 0; j < 8; j++)
        *(float4*)(out + j * 4) = make_float4(acc[j*4], acc[j*4+1],
                                              acc[j*4+2], acc[j*4+3]);
}

// -------------------------------------------------------------------------
// Wt[h*64+m, :] = sum_j w2[h][m][j] * out_proj[h*64+j, :]
// -------------------------------------------------------------------------
__global__ __launch_bounds__(256) void wt_kernel(
    const float* __restrict__ fus_w2, const float* __restrict__ out_proj)
{
    __shared__ float w2s[HDh][HDh];
    __shared__ float ops[HDh][128];

    const int hi = blockIdx.x;
    const int c0 = blockIdx.y * 128;
    const int tid = threadIdx.x;

    const float* w2 = fus_w2 + (long)hi * HDh * HDh;
#pragma unroll
    for (int i = 0; i < 4; i++) {
        int f = i * 256 + tid;
        *(float4*)&w2s[f >> 4][(f & 15) * 4] = *(const float4*)(w2 + f * 4);
    }
#pragma unroll
    for (int i = 0; i < 8; i++) {
        int f = i * 256 + tid;
        int rr = f >> 5, qq = f & 31;
        *(float4*)&ops[rr][qq * 4] =
            *(const float4*)(out_proj + (long)(hi * HDh + rr) * Dd + c0 + qq * 4);
    }
    __syncthreads();

    const int rg = tid >> 5;
    const int tc = tid & 31;
    float accw[8][4];
#pragma unroll
    for (int i = 0; i < 8; i++)
#pragma unroll
        for (int j = 0; j < 4; j++) accw[i][j] = 0.0f;

#pragma unroll 4
    for (int j = 0; j < HDh; j++) {
        float4 ov = *(float4*)&ops[j][tc * 4];
#pragma unroll
        for (int i = 0; i < 8; i++) {
            float w = w2s[rg * 8 + i][j];
            accw[i][0] += w * ov.x;
            accw[i][1] += w * ov.y;
            accw[i][2] += w * ov.z;
            accw[i][3] += w * ov.w;
        }
    }
#pragma unroll
    for (int i = 0; i < 8; i++)
        *(float4*)(g_Wt + (long)(hi * HDh + rg * 8 + i) * Dd + c0 + tc * 4) =
            make_float4(accw[i][0], accw[i][1], accw[i][2], accw[i][3]);
}

// -------------------------------------------------------------------------
// Parallel vec @ mat (deterministic two-stage)
// -------------------------------------------------------------------------
__global__ __launch_bounds__(256) void vecmat_partial(
    const float* __restrict__ vec, const float* __restrict__ mat)
{
    int c  = blockIdx.x * 256 + threadIdx.x;
    int kc = blockIdx.y;
    const float* m = mat + (long)kc * 64 * Dd + c;
    const float* v = vec + kc * 64;
    float s = 0.0f;
#pragma unroll 8
    for (int j = 0; j < 64; j++) s += v[j] * m[(long)j * Dd];
    g_vpart[kc * Dd + c] = s;
}

__global__ __launch_bounds__(256) void vecmat_combine(float* __restrict__ outv)
{
    int c = blockIdx.x * 256 + threadIdx.x;
    float s = 0.0f;
#pragma unroll
    for (int k = 0; k < 16; k++) s += g_vpart[k * Dd + c];
    outv[c] = s;
}

// -------------------------------------------------------------------------
// Tail outputs (constants), only if the output buffer carries them.
// -------------------------------------------------------------------------
__global__ void tail_kernel(float* __restrict__ out, int out_size)
{
    const int base = Rr * Dd;
    int i = blockIdx.x * blockDim.x + threadIdx.x;
    if (out_size >= base + 2 * Rr) {
        float strength = 1.0f - logf(1.0f / (float)Nn + 1e-8f);
        if (i < Rr)            out[base + i] = 1023.0f;
        else if (i < 2 * Rr)   out[base + i] = strength;
    }
}

// -------------------------------------------------------------------------
extern "C" void kernel_launch(void* const* d_in, const int* in_sizes, int n_in,
                              void* d_out, int out_size)
{
    const float* h         = (const float*)d_in[0];
    // d_in[1..8]: fe/be scorer weights -> provably dead (uniform softmax)
    const float* vproj_w   = (const float*)d_in[9];
    const float* fus_w1    = (const float*)d_in[10];
    const float* fus_b1    = (const float*)d_in[11];
    const float* fus_w2    = (const float*)d_in[12];
    const float* fus_b2    = (const float*)d_in[13];
    const float* out_proj  = (const float*)d_in[14];
    const float* o_proj    = (const float*)d_in[15];
    float* z = (float*)d_out;

    float *T_p, *U_p, *Wt_p, *Wbig_p, *c_p, *v1_p, *zb_p;
    cudaGetSymbolAddress((void**)&T_p,    g_T);
    cudaGetSymbolAddress((void**)&U_p,    g_U);
    cudaGetSymbolAddress((void**)&Wt_p,   g_Wt);
    cudaGetSymbolAddress((void**)&Wbig_p, g_Wbig);
    cudaGetSymbolAddress((void**)&c_p,    g_c);
    cudaGetSymbolAddress((void**)&v1_p,   g_v1);
    cudaGetSymbolAddress((void**)&zb_p,   g_zbias);

    static int smem_set = 0;
    if (!smem_set) {
        cudaFuncSetAttribute(gemm_tf32,
                             cudaFuncAttributeMaxDynamicSharedMemorySize,
                             GEMM_SMEM_BYTES);
        smem_set = 1;
    }

    // 0) mean over h rows -> folded bias c ; layer-1 weight fold U ;
    //    w2/out_proj fold Wt ; zbias chain
    {
        dim3 gm(64, Bsz);
        mean_partial_kernel<<<gm, 1024>>>(h);
        mean_combine_kernel<<<Bsz, 1024>>>();
        dim3 gc(Hh, Bsz);
        compute_c_kernel<<<gc, 256>>>(vproj_w, fus_w1, fus_b1);
        dim3 gu(Hh, 8);
        u_kernel<<<gu, 256>>>(vproj_w, fus_w1);
        dim3 gw(Hh, 8);
        wt_kernel<<<gw, 256>>>(fus_w2, out_proj);
        dim3 gv(4, 16);
        vecmat_partial<<<gv, 256>>>(fus_b2, out_proj);
        vecmat_combine<<<4, 256>>>(v1_p);
        vecmat_partial<<<gv, 256>>>(v1_p, o_proj);
        vecmat_combine<<<4, 256>>>(zb_p);
    }

    // 1) packed: T = gelu(h @ U + c)  AND  Wbig = Wt @ o_proj
    gemm_tf32<<<320, 256, GEMM_SMEM_BYTES>>>(
        h, U_p, T_p, c_p, 1,
        Wt_p, o_proj, Wbig_p, (const float*)0, 0, 256);

    // 2) z = T @ Wbig + zbias   (writes directly into d_out)
    gemm_tf32<<<256, 256, GEMM_SMEM_BYTES>>>(
        T_p, Wbig_p, z, zb_p, 2,
        T_p, Wbig_p, z, zb_p, 2, 256);

    // 3) constant tail outputs
    tail_kernel<<<32, 256>>>(z, out_size);
}